// round 16
// baseline (speedup 1.0000x reference)
#include <cuda_runtime.h>

// Problem shapes (fixed by dataset)
#define BB   2
#define CC   64     // channels in
#define OC   64     // channels out
#define KNB  9      // neighbors
#define NMAX 50000
#define TN   32     // nodes per tile

// Scratch: g = relu(W1 @ x + b1), node-major g[b][n][c].
__device__ float g_scratch[(size_t)BB * NMAX * CC];
// Scratch: gmax[b][n][c] = max over 9 neighbors of g.
__device__ float gmax_scratch[(size_t)BB * NMAX * CC];
// Pre-transposed weights (filled by k0 each launch): [c][d] layouts.
__device__ float w1t_g[CC * OC];
__device__ float w2t_g[2 * CC * OC];

// ---- packed f32x2 helpers ---------------------------------------------------
__device__ __forceinline__ unsigned long long pack2(float lo, float hi) {
    unsigned long long r;
    asm("mov.b64 %0, {%1, %2};" : "=l"(r) : "f"(lo), "f"(hi));
    return r;
}
__device__ __forceinline__ void fma2(unsigned long long& acc,
                                     unsigned long long a, unsigned long long b) {
    asm("fma.rn.f32x2 %0, %1, %2, %0;" : "+l"(acc) : "l"(a), "l"(b));
}
__device__ __forceinline__ void unpack2(unsigned long long v, float& lo, float& hi) {
    asm("mov.b64 {%0, %1}, %2;" : "=f"(lo), "=f"(hi) : "l"(v));
}

// Swizzled [ch][nl] index: conflict-free for both nl-lane and ch-lane access.
#define CIDX(ch, nl) ((ch) * TN + (((nl)) ^ ((ch) & 31)))

// ---------------------------------------------------------------------------
// K0: weight transpose into device globals (wide grid -> ~1.5us).
// ---------------------------------------------------------------------------
__global__ void k0_transpose(const float* __restrict__ W1,
                             const float* __restrict__ W2)
{
    int t = blockIdx.x * blockDim.x + threadIdx.x;
    int stride = gridDim.x * blockDim.x;
    for (int e = t; e < CC * OC; e += stride) {
        int d = e >> 6, c = e & 63;           // W1[d][c]
        w1t_g[c * OC + d] = W1[e];
    }
    for (int e = t; e < 2 * CC * OC; e += stride) {
        int d = e >> 7, ch = e & 127;         // W2[d][ch]
        w2t_g[ch * OC + d] = W2[e];
    }
}

// ---------------------------------------------------------------------------
// K1: dense per-node MLP1, tiled. 256 threads = 32 nodes x (64 out / 8 per thr).
//   g[b][n][d] = relu( sum_c W1[d][c]*x[b][c][n] + b1[d] )
// ---------------------------------------------------------------------------
__global__ void __launch_bounds__(256) k1_node_mlp(
    const float* __restrict__ x,
    const float* __restrict__ b1,
    int N)
{
    __shared__ float w1t[CC * OC];    // 16KB [c][d]
    __shared__ float xs[CC * TN];     // 8KB swizzled [c][nl]
    __shared__ float b1s[OC];

    const int t  = threadIdx.x;
    const int b  = blockIdx.y;
    const int n0 = blockIdx.x * TN;

    {   // linear float4 copy of pre-transposed W1 (conflict-free)
        const float4* src = (const float4*)w1t_g;
        float4* dst = (float4*)w1t;
        #pragma unroll
        for (int i = 0; i < (CC * OC / 4) / 256; i++)
            dst[t + i * 256] = src[t + i * 256];
    }
    if (t < OC) b1s[t] = b1[t];

    // x tile: coalesced loads, swizzled stores
    #pragma unroll
    for (int i = 0; i < (CC * TN) / 256; i++) {
        int e  = t + i * 256;
        int c  = e >> 5, nl = e & 31;
        int n  = n0 + nl;
        xs[CIDX(c, nl)] = (n < N) ? x[((size_t)b * CC + c) * N + n] : 0.f;
    }
    __syncthreads();

    const int nl = t & 31;
    const int d0 = (t >> 5) * 8;
    const int n  = n0 + nl;

    unsigned long long acc2[4];
    #pragma unroll
    for (int j = 0; j < 4; j++) acc2[j] = 0ull;

    #pragma unroll 4
    for (int ch = 0; ch < CC; ch++) {
        float v = xs[CIDX(ch, nl)];
        unsigned long long v2 = pack2(v, v);
        const ulonglong2* wp = (const ulonglong2*)(w1t + ch * OC + d0);
        ulonglong2 wa = wp[0], wb = wp[1];    // broadcast LDS.128
        fma2(acc2[0], wa.x, v2);
        fma2(acc2[1], wa.y, v2);
        fma2(acc2[2], wb.x, v2);
        fma2(acc2[3], wb.y, v2);
    }

    if (n < N) {
        float r[8];
        unpack2(acc2[0], r[0], r[1]);
        unpack2(acc2[1], r[2], r[3]);
        unpack2(acc2[2], r[4], r[5]);
        unpack2(acc2[3], r[6], r[7]);
        float* gp = g_scratch + ((size_t)b * N + n) * CC + d0;
        float4 o0, o1;
        o0.x = fmaxf(r[0] + b1s[d0 + 0], 0.f);
        o0.y = fmaxf(r[1] + b1s[d0 + 1], 0.f);
        o0.z = fmaxf(r[2] + b1s[d0 + 2], 0.f);
        o0.w = fmaxf(r[3] + b1s[d0 + 3], 0.f);
        o1.x = fmaxf(r[4] + b1s[d0 + 4], 0.f);
        o1.y = fmaxf(r[5] + b1s[d0 + 5], 0.f);
        o1.z = fmaxf(r[6] + b1s[d0 + 6], 0.f);
        o1.w = fmaxf(r[7] + b1s[d0 + 7], 0.f);
        ((float4*)gp)[0] = o0;
        ((float4*)gp)[1] = o1;
    }
}

// ---------------------------------------------------------------------------
// K2a: gather-max only. Barrier-free, smem-free, max occupancy, streaming.
// Warp handles 4 nodes; lane l owns channels l and l+32 of each node.
// ---------------------------------------------------------------------------
__global__ void __launch_bounds__(256) k2a_gather(
    const int* __restrict__ edge,     // edge_index[0]: [B][N][K] int32
    int N)
{
    const int t  = threadIdx.x;
    const int b  = blockIdx.y;
    const int n0 = blockIdx.x * TN;
    const int w  = t >> 5, l = t & 31;

    #pragma unroll
    for (int j = 0; j < 4; j++) {
        int nl = w * 4 + j;
        int n  = n0 + nl;
        if (n < N) {
            const int* ep = edge + ((size_t)b * N + n) * KNB;
            float m0 = 0.f, m1 = 0.f;   // relu >= 0, so 0 acts as -inf
            #pragma unroll
            for (int k = 0; k < KNB; k++) {
                int m = ep[k];                     // broadcast load in warp
                m = min(max(m, 0), N - 1);         // defensive clamp
                const float* gp = g_scratch + ((size_t)b * N + m) * CC;
                m0 = fmaxf(m0, gp[l]);             // coalesced 128B
                m1 = fmaxf(m1, gp[32 + l]);        // coalesced 128B
            }
            float* op = gmax_scratch + ((size_t)b * N + n) * CC;
            op[l]      = m0;                       // coalesced
            op[32 + l] = m1;
        }
    }
}

// ---------------------------------------------------------------------------
// K2b: dense MLP2. cats = [x ; gmax] staged in swizzled smem, 64x128 matvec.
// No latency phase: should run near the FMA/LDS throughput bound.
// ---------------------------------------------------------------------------
__global__ void __launch_bounds__(256) k2b_mlp(
    const float* __restrict__ x,
    const float* __restrict__ b2,
    float*       __restrict__ out,
    int N)
{
    __shared__ float cats[2 * CC * TN];   // 16KB swizzled [ch][nl]
    __shared__ float w2t[2 * CC * OC];    // 32KB [ch][d]

    const int t  = threadIdx.x;
    const int b  = blockIdx.y;
    const int n0 = blockIdx.x * TN;

    {   // linear float4 copy of pre-transposed W2 (conflict-free)
        const float4* src = (const float4*)w2t_g;
        float4* dst = (float4*)w2t;
        #pragma unroll
        for (int i = 0; i < (2 * CC * OC / 4) / 256; i++)
            dst[t + i * 256] = src[t + i * 256];
    }

    // x tile -> cats channels [0,64): coalesced over n
    #pragma unroll
    for (int i = 0; i < (CC * TN) / 256; i++) {
        int e  = t + i * 256;
        int c  = e >> 5, nl = e & 31;
        int n  = n0 + nl;
        cats[CIDX(c, nl)] = (n < N) ? x[((size_t)b * CC + c) * N + n] : 0.f;
    }

    // gmax tile -> cats channels [64,128): node-major, coalesced over c
    #pragma unroll
    for (int i = 0; i < (CC * TN) / 256; i++) {
        int e  = t + i * 256;
        int c  = e & 63, nl = e >> 6;     // lanes -> consecutive c: coalesced
        int n  = n0 + nl;
        cats[CIDX(CC + c, nl)] =
            (n < N) ? gmax_scratch[((size_t)b * N + n) * CC + c] : 0.f;
    }
    __syncthreads();

    // Matvec: thread = (node nl, 8 output channels d0..d0+7), f32x2-packed.
    const int nl = t & 31;
    const int d0 = (t >> 5) * 8;
    const int n  = n0 + nl;

    unsigned long long acc2[4];
    #pragma unroll
    for (int j = 0; j < 4; j++) acc2[j] = 0ull;

    #pragma unroll 4
    for (int ch = 0; ch < 2 * CC; ch++) {
        float v = cats[CIDX(ch, nl)];
        unsigned long long v2 = pack2(v, v);
        const ulonglong2* wp = (const ulonglong2*)(w2t + ch * OC + d0);
        ulonglong2 wa = wp[0], wb = wp[1];    // broadcast LDS.128
        fma2(acc2[0], wa.x, v2);
        fma2(acc2[1], wa.y, v2);
        fma2(acc2[2], wb.x, v2);
        fma2(acc2[3], wb.y, v2);
    }

    if (n < N) {
        float r[8];
        unpack2(acc2[0], r[0], r[1]);
        unpack2(acc2[1], r[2], r[3]);
        unpack2(acc2[2], r[4], r[5]);
        unpack2(acc2[3], r[6], r[7]);
        #pragma unroll
        for (int j = 0; j < 8; j++) {
            float bias = __ldg(&b2[d0 + j]);
            out[((size_t)b * OC + d0 + j) * N + n] = fmaxf(r[j] + bias, 0.f);
        }
    }
}

// ---------------------------------------------------------------------------
extern "C" void kernel_launch(void* const* d_in, const int* in_sizes, int n_in,
                              void* d_out, int out_size)
{
    const float* x    = (const float*)d_in[0];      // [B,C,N,1] f32
    const int*   edge = (const int*)d_in[1];        // [2,B,N,K] int32 (use [0])
    const float* W1   = (const float*)d_in[2];      // [C,C]
    const float* b1   = (const float*)d_in[3];      // [C]
    const float* W2   = (const float*)d_in[4];      // [OC,2C]
    const float* b2   = (const float*)d_in[5];      // [OC]
    float*       out  = (float*)d_out;              // [B,OC,N,1]

    const int N = in_sizes[0] / (BB * CC);
    const int nt = (N + TN - 1) / TN;

    k0_transpose<<<64, 256>>>(W1, W2);

    dim3 g(nt, BB);
    k1_node_mlp<<<g, 256>>>(x, b1, N);
    k2a_gather <<<g, 256>>>(edge, N);
    k2b_mlp    <<<g, 256>>>(x, b2, out, N);
}

// round 17
// speedup vs baseline: 1.0024x; 1.0024x over previous
#include <cuda_runtime.h>

// Problem shapes (fixed by dataset)
#define BB   2
#define CC   64     // channels in
#define OC   64     // channels out
#define KNB  9      // neighbors
#define NMAX 50000
#define TN   32     // nodes per tile

// Scratch: g = relu(W1 @ x + b1), node-major g[b][n][c].
__device__ float g_scratch[(size_t)BB * NMAX * CC];
// Scratch: gmax[b][n][c] = max over 9 neighbors of g.
__device__ float gmax_scratch[(size_t)BB * NMAX * CC];
// Pre-transposed weights (filled by k0 each launch): [c][d] layouts.
__device__ float w1t_g[CC * OC];
__device__ float w2t_g[2 * CC * OC];

// ---- packed f32x2 helpers ---------------------------------------------------
__device__ __forceinline__ unsigned long long pack2(float lo, float hi) {
    unsigned long long r;
    asm("mov.b64 %0, {%1, %2};" : "=l"(r) : "f"(lo), "f"(hi));
    return r;
}
__device__ __forceinline__ void fma2(unsigned long long& acc,
                                     unsigned long long a, unsigned long long b) {
    asm("fma.rn.f32x2 %0, %1, %2, %0;" : "+l"(acc) : "l"(a), "l"(b));
}
__device__ __forceinline__ void unpack2(unsigned long long v, float& lo, float& hi) {
    asm("mov.b64 {%0, %1}, %2;" : "=f"(lo), "=f"(hi) : "l"(v));
}

// Swizzled [ch][nl] index: conflict-free for both nl-lane and ch-lane access.
#define CIDX(ch, nl) ((ch) * TN + (((nl)) ^ ((ch) & 31)))

// ---------------------------------------------------------------------------
// K0: weight transpose into device globals (wide grid -> ~1.5us).
// ---------------------------------------------------------------------------
__global__ void k0_transpose(const float* __restrict__ W1,
                             const float* __restrict__ W2)
{
    int t = blockIdx.x * blockDim.x + threadIdx.x;
    int stride = gridDim.x * blockDim.x;
    for (int e = t; e < CC * OC; e += stride) {
        int d = e >> 6, c = e & 63;           // W1[d][c]
        w1t_g[c * OC + d] = W1[e];
    }
    for (int e = t; e < 2 * CC * OC; e += stride) {
        int d = e >> 7, ch = e & 127;         // W2[d][ch]
        w2t_g[ch * OC + d] = W2[e];
    }
}

// ---------------------------------------------------------------------------
// K1: dense per-node MLP1, tiled. 256 threads = 32 nodes x (64 out / 8 per thr).
//   g[b][n][d] = relu( sum_c W1[d][c]*x[b][c][n] + b1[d] )
// ---------------------------------------------------------------------------
__global__ void __launch_bounds__(256) k1_node_mlp(
    const float* __restrict__ x,
    const float* __restrict__ b1,
    int N)
{
    __shared__ float w1t[CC * OC];    // 16KB [c][d]
    __shared__ float xs[CC * TN];     // 8KB swizzled [c][nl]
    __shared__ float b1s[OC];

    const int t  = threadIdx.x;
    const int b  = blockIdx.y;
    const int n0 = blockIdx.x * TN;

    {   // linear float4 copy of pre-transposed W1 (conflict-free)
        const float4* src = (const float4*)w1t_g;
        float4* dst = (float4*)w1t;
        #pragma unroll
        for (int i = 0; i < (CC * OC / 4) / 256; i++)
            dst[t + i * 256] = src[t + i * 256];
    }
    if (t < OC) b1s[t] = b1[t];

    // x tile: coalesced loads, swizzled stores
    #pragma unroll
    for (int i = 0; i < (CC * TN) / 256; i++) {
        int e  = t + i * 256;
        int c  = e >> 5, nl = e & 31;
        int n  = n0 + nl;
        xs[CIDX(c, nl)] = (n < N) ? x[((size_t)b * CC + c) * N + n] : 0.f;
    }
    __syncthreads();

    const int nl = t & 31;
    const int d0 = (t >> 5) * 8;
    const int n  = n0 + nl;

    unsigned long long acc2[4];
    #pragma unroll
    for (int j = 0; j < 4; j++) acc2[j] = 0ull;

    #pragma unroll 4
    for (int ch = 0; ch < CC; ch++) {
        float v = xs[CIDX(ch, nl)];
        unsigned long long v2 = pack2(v, v);
        const ulonglong2* wp = (const ulonglong2*)(w1t + ch * OC + d0);
        ulonglong2 wa = wp[0], wb = wp[1];    // broadcast LDS.128
        fma2(acc2[0], wa.x, v2);
        fma2(acc2[1], wa.y, v2);
        fma2(acc2[2], wb.x, v2);
        fma2(acc2[3], wb.y, v2);
    }

    if (n < N) {
        float r[8];
        unpack2(acc2[0], r[0], r[1]);
        unpack2(acc2[1], r[2], r[3]);
        unpack2(acc2[2], r[4], r[5]);
        unpack2(acc2[3], r[6], r[7]);
        float* gp = g_scratch + ((size_t)b * N + n) * CC + d0;
        float4 o0, o1;
        o0.x = fmaxf(r[0] + b1s[d0 + 0], 0.f);
        o0.y = fmaxf(r[1] + b1s[d0 + 1], 0.f);
        o0.z = fmaxf(r[2] + b1s[d0 + 2], 0.f);
        o0.w = fmaxf(r[3] + b1s[d0 + 3], 0.f);
        o1.x = fmaxf(r[4] + b1s[d0 + 4], 0.f);
        o1.y = fmaxf(r[5] + b1s[d0 + 5], 0.f);
        o1.z = fmaxf(r[6] + b1s[d0 + 6], 0.f);
        o1.w = fmaxf(r[7] + b1s[d0 + 7], 0.f);
        ((float4*)gp)[0] = o0;
        ((float4*)gp)[1] = o1;
    }
}

// ---------------------------------------------------------------------------
// K2a: gather-max only. Barrier-free, smem-free, max occupancy, streaming.
// Warp handles 4 nodes; lane l owns channels l and l+32 of each node.
// ---------------------------------------------------------------------------
__global__ void __launch_bounds__(256) k2a_gather(
    const int* __restrict__ edge,     // edge_index[0]: [B][N][K] int32
    int N)
{
    const int t  = threadIdx.x;
    const int b  = blockIdx.y;
    const int n0 = blockIdx.x * TN;
    const int w  = t >> 5, l = t & 31;

    #pragma unroll
    for (int j = 0; j < 4; j++) {
        int nl = w * 4 + j;
        int n  = n0 + nl;
        if (n < N) {
            const int* ep = edge + ((size_t)b * N + n) * KNB;
            float m0 = 0.f, m1 = 0.f;   // relu >= 0, so 0 acts as -inf
            #pragma unroll
            for (int k = 0; k < KNB; k++) {
                int m = ep[k];                     // broadcast load in warp
                m = min(max(m, 0), N - 1);         // defensive clamp
                const float* gp = g_scratch + ((size_t)b * N + m) * CC;
                m0 = fmaxf(m0, gp[l]);             // coalesced 128B
                m1 = fmaxf(m1, gp[32 + l]);        // coalesced 128B
            }
            float* op = gmax_scratch + ((size_t)b * N + n) * CC;
            op[l]      = m0;                       // coalesced
            op[32 + l] = m1;
        }
    }
}

// ---------------------------------------------------------------------------
// K2b: dense MLP2. cats = [x ; gmax] staged in swizzled smem, 64x128 matvec.
// No latency phase: should run near the FMA/LDS throughput bound.
// ---------------------------------------------------------------------------
__global__ void __launch_bounds__(256) k2b_mlp(
    const float* __restrict__ x,
    const float* __restrict__ b2,
    float*       __restrict__ out,
    int N)
{
    __shared__ float cats[2 * CC * TN];   // 16KB swizzled [ch][nl]
    __shared__ float w2t[2 * CC * OC];    // 32KB [ch][d]

    const int t  = threadIdx.x;
    const int b  = blockIdx.y;
    const int n0 = blockIdx.x * TN;

    {   // linear float4 copy of pre-transposed W2 (conflict-free)
        const float4* src = (const float4*)w2t_g;
        float4* dst = (float4*)w2t;
        #pragma unroll
        for (int i = 0; i < (2 * CC * OC / 4) / 256; i++)
            dst[t + i * 256] = src[t + i * 256];
    }

    // x tile -> cats channels [0,64): coalesced over n
    #pragma unroll
    for (int i = 0; i < (CC * TN) / 256; i++) {
        int e  = t + i * 256;
        int c  = e >> 5, nl = e & 31;
        int n  = n0 + nl;
        cats[CIDX(c, nl)] = (n < N) ? x[((size_t)b * CC + c) * N + n] : 0.f;
    }

    // gmax tile -> cats channels [64,128): node-major, coalesced over c
    #pragma unroll
    for (int i = 0; i < (CC * TN) / 256; i++) {
        int e  = t + i * 256;
        int c  = e & 63, nl = e >> 6;     // lanes -> consecutive c: coalesced
        int n  = n0 + nl;
        cats[CIDX(CC + c, nl)] =
            (n < N) ? gmax_scratch[((size_t)b * N + n) * CC + c] : 0.f;
    }
    __syncthreads();

    // Matvec: thread = (node nl, 8 output channels d0..d0+7), f32x2-packed.
    const int nl = t & 31;
    const int d0 = (t >> 5) * 8;
    const int n  = n0 + nl;

    unsigned long long acc2[4];
    #pragma unroll
    for (int j = 0; j < 4; j++) acc2[j] = 0ull;

    #pragma unroll 4
    for (int ch = 0; ch < 2 * CC; ch++) {
        float v = cats[CIDX(ch, nl)];
        unsigned long long v2 = pack2(v, v);
        const ulonglong2* wp = (const ulonglong2*)(w2t + ch * OC + d0);
        ulonglong2 wa = wp[0], wb = wp[1];    // broadcast LDS.128
        fma2(acc2[0], wa.x, v2);
        fma2(acc2[1], wa.y, v2);
        fma2(acc2[2], wb.x, v2);
        fma2(acc2[3], wb.y, v2);
    }

    if (n < N) {
        float r[8];
        unpack2(acc2[0], r[0], r[1]);
        unpack2(acc2[1], r[2], r[3]);
        unpack2(acc2[2], r[4], r[5]);
        unpack2(acc2[3], r[6], r[7]);
        #pragma unroll
        for (int j = 0; j < 8; j++) {
            float bias = __ldg(&b2[d0 + j]);
            out[((size_t)b * OC + d0 + j) * N + n] = fmaxf(r[j] + bias, 0.f);
        }
    }
}

// ---------------------------------------------------------------------------
extern "C" void kernel_launch(void* const* d_in, const int* in_sizes, int n_in,
                              void* d_out, int out_size)
{
    const float* x    = (const float*)d_in[0];      // [B,C,N,1] f32
    const int*   edge = (const int*)d_in[1];        // [2,B,N,K] int32 (use [0])
    const float* W1   = (const float*)d_in[2];      // [C,C]
    const float* b1   = (const float*)d_in[3];      // [C]
    const float* W2   = (const float*)d_in[4];      // [OC,2C]
    const float* b2   = (const float*)d_in[5];      // [OC]
    float*       out  = (float*)d_out;              // [B,OC,N,1]

    const int N = in_sizes[0] / (BB * CC);
    const int nt = (N + TN - 1) / TN;

    k0_transpose<<<64, 256>>>(W1, W2);

    dim3 g(nt, BB);
    k1_node_mlp<<<g, 256>>>(x, b1, N);
    k2a_gather <<<g, 256>>>(edge, N);
    k2b_mlp    <<<g, 256>>>(x, b2, out, N);
}